// round 1
// baseline (speedup 1.0000x reference)
#include <cuda_runtime.h>
#include <math.h>

// Problem dims
#define BB   2
#define CCH  16
#define HH   128
#define WW   128
#define MM   9
#define NDD  9
#define MCC  144          // MM*CCH
#define HIDN 18
#define OUTC 150
#define HWD  (HH*WW*NDD)  // 147456
#define EPSBN 1e-5f

// Scratch (device globals; no runtime allocation allowed)
__device__ float g_cv [BB*(size_t)MCC*HWD];   // cost volume  [b][mc][h][w][d]  ~170MB
__device__ float g_h1 [BB*(size_t)HIDN*HWD];  // hidden       [b][o][h][w][d]   ~21MB
__device__ float g_wei[BB*(size_t)MM*HWD];    // sigmoid attn [b][m][h][w][d]   ~10.6MB
__device__ float g_p  [BB*MCC];               // global mean pool
__device__ float g_xg [BB*MM];                // global-branch logits

// ---------------------------------------------------------------------------
// K1: build cost volume.  cv[b,mc,h,w,d] = x[b,c,h, w+(d-4)*(m-4), m] (0 outside)
// x layout: [B][C][H][W][M]
// ---------------------------------------------------------------------------
__global__ void k_build_cv(const float* __restrict__ x) {
    unsigned idx = blockIdx.x * blockDim.x + threadIdx.x;   // total 42,467,328
    if (idx >= (unsigned)(BB*MCC*HWD)) return;
    unsigned i = idx;
    int d  = i % NDD;  i /= NDD;
    int w  = i % WW;   i /= WW;
    int h  = i % HH;   i /= HH;
    int mc = i % MCC;  i /= MCC;
    int b  = i;
    int m = mc / CCH, c = mc % CCH;
    int ws = w + (d - 4) * (m - 4);
    float v = 0.f;
    if ((unsigned)ws < WW)
        v = x[(((size_t)(b*CCH + c)*HH + h)*WW + ws)*MM + m];
    g_cv[idx] = v;
}

// ---------------------------------------------------------------------------
// K2: mean pool over (h,w,d) per (b,mc). One block per (b,mc). Deterministic.
// ---------------------------------------------------------------------------
__global__ void k_reduce() {
    int bm = blockIdx.x;                      // 0..287
    const float* src = g_cv + (size_t)bm * HWD;
    float s = 0.f;
    for (int i = threadIdx.x; i < HWD; i += 256) s += src[i];
    __shared__ float sh[256];
    sh[threadIdx.x] = s;
    __syncthreads();
    for (int o = 128; o > 0; o >>= 1) {
        if (threadIdx.x < o) sh[threadIdx.x] += sh[threadIdx.x + o];
        __syncthreads();
    }
    if (threadIdx.x == 0) g_p[bm] = sh[0] * (1.0f / HWD);
}

// ---------------------------------------------------------------------------
// K3: global attention branch. conv3d(pad=1) on 1x1x1 spatial == center tap.
// ---------------------------------------------------------------------------
__global__ void k_global(const float* __restrict__ w1, const float* __restrict__ b1,
                         const float* __restrict__ g1, const float* __restrict__ be1,
                         const float* __restrict__ m1, const float* __restrict__ v1,
                         const float* __restrict__ w2, const float* __restrict__ b2,
                         const float* __restrict__ g2, const float* __restrict__ be2,
                         const float* __restrict__ m2, const float* __restrict__ v2) {
    __shared__ float gh[BB*HIDN];
    int t = threadIdx.x;
    if (t < BB*HIDN) {
        int b = t / HIDN, o = t % HIDN;
        float s = b1[o];
        for (int c = 0; c < MCC; c++)
            s += w1[(o*MCC + c)*27 + 13] * g_p[b*MCC + c];
        float sc = g1[o] * rsqrtf(v1[o] + EPSBN);
        s = (s - m1[o]) * sc + be1[o];
        gh[t] = fmaxf(s, 0.f);
    }
    __syncthreads();
    if (t < BB*MM) {
        int b = t / MM, og = t % MM;
        float s = b2[og];
        for (int o = 0; o < HIDN; o++)
            s += w2[(og*HIDN + o)*27 + 13] * gh[b*HIDN + o];
        float sc = g2[og] * rsqrtf(v2[og] + EPSBN);
        g_xg[t] = (s - m2[og]) * sc + be2[og];
    }
}

// ---------------------------------------------------------------------------
// K4: conv1 (144 -> 18, 3x3x3, pad 1) + BN + ReLU.
// grid (W/16, H/16, B*ND), block 16x16. Each thread: one (h,w), all 18 oc,
// one d_out. smem: 3 d-slices of 18x18 cv tile + 486 weights per mc.
// ---------------------------------------------------------------------------
__global__ __launch_bounds__(256) void k_conv1(
        const float* __restrict__ w1, const float* __restrict__ b1,
        const float* __restrict__ g1, const float* __restrict__ be1,
        const float* __restrict__ m1, const float* __restrict__ v1) {
    __shared__ float tile[3][18][18];
    __shared__ float wsh[HIDN*27];
    __shared__ float sc[HIDN], bi[HIDN];

    int tx = threadIdx.x & 15, ty = threadIdx.x >> 4;
    int b = blockIdx.z / NDD, dout = blockIdx.z % NDD;
    int h0 = blockIdx.y * 16, w0 = blockIdx.x * 16;

    if (threadIdx.x < HIDN) {
        float s = g1[threadIdx.x] * rsqrtf(v1[threadIdx.x] + EPSBN);
        sc[threadIdx.x] = s;
        bi[threadIdx.x] = (b1[threadIdx.x] - m1[threadIdx.x]) * s + be1[threadIdx.x];
    }

    float acc[HIDN];
#pragma unroll
    for (int o = 0; o < HIDN; o++) acc[o] = 0.f;

    for (int mc = 0; mc < MCC; mc++) {
        __syncthreads();  // previous iteration's compute done before smem overwrite
        // weights: coalesced, layout wsh[o*27+tap]
        for (int t = threadIdx.x; t < HIDN*27; t += 256)
            wsh[t] = w1[(size_t)( (t/27)*MCC + mc )*27 + (t % 27)];
        // cv tile: 3 x 18 x 18 with zero halo
        const float* cvb = g_cv + (size_t)(b*MCC + mc) * HWD;
        for (int t = threadIdx.x; t < 3*18*18; t += 256) {
            int j = t % 18, tt = t / 18;
            int i = tt % 18, zi = tt / 18;
            int hh = h0 - 1 + i, ww = w0 - 1 + j, dd = dout - 1 + zi;
            float v = 0.f;
            if ((unsigned)hh < HH && (unsigned)ww < WW && (unsigned)dd < NDD)
                v = cvb[(hh*WW + ww)*NDD + dd];
            tile[zi][i][j] = v;
        }
        __syncthreads();
#pragma unroll
        for (int k0 = 0; k0 < 3; k0++)
#pragma unroll
        for (int k1 = 0; k1 < 3; k1++)
#pragma unroll
        for (int k2 = 0; k2 < 3; k2++) {
            float v = tile[k2][ty + k0][tx + k1];
            int tap = k0*9 + k1*3 + k2;
#pragma unroll
            for (int o = 0; o < HIDN; o++)
                acc[o] = fmaf(v, wsh[o*27 + tap], acc[o]);
        }
    }

    int h = h0 + ty, w = w0 + tx;
    float* dst = g_h1 + (size_t)(b*HIDN)*HWD + (h*WW + w)*NDD + dout;
#pragma unroll
    for (int o = 0; o < HIDN; o++)
        dst[(size_t)o * HWD] = fmaxf(acc[o]*sc[o] + bi[o], 0.f);
}

// ---------------------------------------------------------------------------
// K5: conv2 (18 -> 9, 3x3x3, pad 1) + BN + add global + sigmoid -> g_wei.
// ---------------------------------------------------------------------------
__global__ __launch_bounds__(256) void k_conv2(
        const float* __restrict__ w2, const float* __restrict__ b2,
        const float* __restrict__ g2, const float* __restrict__ be2,
        const float* __restrict__ m2, const float* __restrict__ v2) {
    __shared__ float tile[3][18][18];
    __shared__ float wsh[MM*27];
    __shared__ float sc[MM], bi[MM];

    int tx = threadIdx.x & 15, ty = threadIdx.x >> 4;
    int b = blockIdx.z / NDD, dout = blockIdx.z % NDD;
    int h0 = blockIdx.y * 16, w0 = blockIdx.x * 16;

    if (threadIdx.x < MM) {
        float s = g2[threadIdx.x] * rsqrtf(v2[threadIdx.x] + EPSBN);
        sc[threadIdx.x] = s;
        bi[threadIdx.x] = (b2[threadIdx.x] - m2[threadIdx.x]) * s + be2[threadIdx.x];
    }

    float acc[MM];
#pragma unroll
    for (int o = 0; o < MM; o++) acc[o] = 0.f;

    for (int ci = 0; ci < HIDN; ci++) {
        __syncthreads();
        for (int t = threadIdx.x; t < MM*27; t += 256)
            wsh[t] = w2[(size_t)( (t/27)*HIDN + ci )*27 + (t % 27)];
        const float* hb = g_h1 + (size_t)(b*HIDN + ci) * HWD;
        for (int t = threadIdx.x; t < 3*18*18; t += 256) {
            int j = t % 18, tt = t / 18;
            int i = tt % 18, zi = tt / 18;
            int hh = h0 - 1 + i, ww = w0 - 1 + j, dd = dout - 1 + zi;
            float v = 0.f;
            if ((unsigned)hh < HH && (unsigned)ww < WW && (unsigned)dd < NDD)
                v = hb[(hh*WW + ww)*NDD + dd];
            tile[zi][i][j] = v;
        }
        __syncthreads();
#pragma unroll
        for (int k0 = 0; k0 < 3; k0++)
#pragma unroll
        for (int k1 = 0; k1 < 3; k1++)
#pragma unroll
        for (int k2 = 0; k2 < 3; k2++) {
            float v = tile[k2][ty + k0][tx + k1];
            int tap = k0*9 + k1*3 + k2;
#pragma unroll
            for (int o = 0; o < MM; o++)
                acc[o] = fmaf(v, wsh[o*27 + tap], acc[o]);
        }
    }

    int h = h0 + ty, w = w0 + tx;
#pragma unroll
    for (int o = 0; o < MM; o++) {
        float xl = acc[o]*sc[o] + bi[o] + g_xg[b*MM + o];
        float wei = 1.f / (1.f + expf(-xl));
        g_wei[(size_t)(b*MM + o)*HWD + (h*WW + w)*NDD + dout] = wei;
    }
}

// ---------------------------------------------------------------------------
// K6: conv_last as GEMM.  Out[b][oc][p] = clb[oc] + sum_mc CLW[oc][mc]*A[mc][p]
// A[mc][p] = wei[b][mc/16][p] * cv[b][mc][p],  p over H*W*ND (contiguous).
// block: p-tile of 128; smem A[144][128] + W[152][144]; thread = 19 oc x 4 p.
// ---------------------------------------------------------------------------
extern __shared__ float s_fin[];
__global__ __launch_bounds__(256) void k_final(
        const float* __restrict__ clw, const float* __restrict__ clb,
        float* __restrict__ out) {
    float* As = s_fin;                 // 144*128
    float* Ws = s_fin + 144*128;       // 152*144 (rows 150,151 zero)

    int b  = blockIdx.y;
    int p0 = blockIdx.x * 128;

    for (int t = threadIdx.x; t < 152*144; t += 256) {
        int oc = t / 144, mc = t % 144;
        Ws[t] = (oc < OUTC) ? clw[oc*MCC + mc] : 0.f;
    }
    const float* cvb = g_cv  + (size_t)b*MCC*HWD + p0;
    const float* wb  = g_wei + (size_t)b*MM *HWD + p0;
    for (int t = threadIdx.x; t < 144*128; t += 256) {
        int mc = t / 128, p = t % 128;
        As[t] = cvb[(size_t)mc*HWD + p] * wb[(size_t)(mc >> 4)*HWD + p];
    }
    __syncthreads();

    int tx = threadIdx.x & 31, ty = threadIdx.x >> 5;
    int oc0 = ty * 19;
    float acc[19][4];
#pragma unroll
    for (int j = 0; j < 19; j++)
#pragma unroll
        for (int i = 0; i < 4; i++) acc[j][i] = 0.f;

    for (int k = 0; k < 144; k++) {
        float4 a = *(const float4*)(As + k*128 + tx*4);
#pragma unroll
        for (int j = 0; j < 19; j++) {
            float wv = Ws[(oc0 + j)*144 + k];
            acc[j][0] = fmaf(wv, a.x, acc[j][0]);
            acc[j][1] = fmaf(wv, a.y, acc[j][1]);
            acc[j][2] = fmaf(wv, a.z, acc[j][2]);
            acc[j][3] = fmaf(wv, a.w, acc[j][3]);
        }
    }

#pragma unroll
    for (int j = 0; j < 19; j++) {
        int oc = oc0 + j;
        if (oc < OUTC) {
            float bv = clb[oc];
            float4 r = make_float4(acc[j][0]+bv, acc[j][1]+bv, acc[j][2]+bv, acc[j][3]+bv);
            *(float4*)(out + (size_t)(b*OUTC + oc)*HWD + p0 + tx*4) = r;
        }
    }
}

// ---------------------------------------------------------------------------
extern "C" void kernel_launch(void* const* d_in, const int* in_sizes, int n_in,
                              void* d_out, int out_size) {
    const float* x       = (const float*)d_in[0];
    const float* la_w1   = (const float*)d_in[1];
    const float* la_b1   = (const float*)d_in[2];
    const float* la_g1   = (const float*)d_in[3];
    const float* la_be1  = (const float*)d_in[4];
    const float* la_m1   = (const float*)d_in[5];
    const float* la_v1   = (const float*)d_in[6];
    const float* la_w2   = (const float*)d_in[7];
    const float* la_b2   = (const float*)d_in[8];
    const float* la_g2   = (const float*)d_in[9];
    const float* la_be2  = (const float*)d_in[10];
    const float* la_m2   = (const float*)d_in[11];
    const float* la_v2   = (const float*)d_in[12];
    const float* ga_w1   = (const float*)d_in[13];
    const float* ga_b1   = (const float*)d_in[14];
    const float* ga_g1   = (const float*)d_in[15];
    const float* ga_be1  = (const float*)d_in[16];
    const float* ga_m1   = (const float*)d_in[17];
    const float* ga_v1   = (const float*)d_in[18];
    const float* ga_w2   = (const float*)d_in[19];
    const float* ga_b2   = (const float*)d_in[20];
    const float* ga_g2   = (const float*)d_in[21];
    const float* ga_be2  = (const float*)d_in[22];
    const float* ga_m2   = (const float*)d_in[23];
    const float* ga_v2   = (const float*)d_in[24];
    const float* cl_w    = (const float*)d_in[25];
    const float* cl_b    = (const float*)d_in[26];
    float* out = (float*)d_out;

    // 1) cost volume
    unsigned ncv = BB*MCC*HWD;
    k_build_cv<<<(ncv + 255)/256, 256>>>(x);
    // 2) global mean pool
    k_reduce<<<BB*MCC, 256>>>();
    // 3) global attention logits
    k_global<<<1, 64>>>(ga_w1, ga_b1, ga_g1, ga_be1, ga_m1, ga_v1,
                        ga_w2, ga_b2, ga_g2, ga_be2, ga_m2, ga_v2);
    // 4) local conv1 + BN + ReLU
    dim3 gc(WW/16, HH/16, BB*NDD);
    k_conv1<<<gc, 256>>>(la_w1, la_b1, la_g1, la_be1, la_m1, la_v1);
    // 5) local conv2 + BN + global add + sigmoid
    k_conv2<<<gc, 256>>>(la_w2, la_b2, la_g2, la_be2, la_m2, la_v2);
    // 6) weighted cost volume -> conv_last (GEMM)
    const int smem_bytes = (144*128 + 152*144) * 4;   // 161280
    cudaFuncSetAttribute(k_final, cudaFuncAttributeMaxDynamicSharedMemorySize, smem_bytes);
    dim3 gf(HWD/128, BB);
    k_final<<<gf, 256, smem_bytes>>>(cl_w, cl_b, out);
}

// round 2
// speedup vs baseline: 1.1462x; 1.1462x over previous
#include <cuda_runtime.h>
#include <math.h>

// Problem dims
#define BB   2
#define CCH  16
#define HH   128
#define WW   128
#define MM   9
#define NDD  9
#define MCC  144
#define HIDN 18
#define OUTC 150
#define HWD  (HH*WW*NDD)   // 147456
#define EPSBN 1e-5f

// Scratch (device globals; no runtime allocation allowed)
__device__ float g_cv [BB*(size_t)MCC*HWD];   // cost volume  [b][mc][h][w][d]
__device__ float g_h1 [BB*(size_t)HIDN*HWD];  // hidden
__device__ float g_wei[BB*(size_t)MM*HWD];    // sigmoid attention
__device__ float g_p  [BB*MCC];               // global mean pool
__device__ float g_xg [BB*MM];                // global-branch logits
__device__ float g_w1p[2*MCC*27*18];          // conv1 weights dup-packed [g][mc][tap][2*oc]
__device__ float g_w2p[HIDN*27*18];           // conv2 weights dup-packed [ci][tap][2*oc]

typedef unsigned long long u64;

__device__ __forceinline__ u64 pk2(float lo, float hi) {
    u64 r;
    asm("mov.b64 %0, {%1, %2};" : "=l"(r) : "r"(__float_as_uint(lo)), "r"(__float_as_uint(hi)));
    return r;
}
__device__ __forceinline__ void upk2(float &lo, float &hi, u64 v) {
    unsigned a, b;
    asm("mov.b64 {%0, %1}, %2;" : "=r"(a), "=r"(b) : "l"(v));
    lo = __uint_as_float(a); hi = __uint_as_float(b);
}
__device__ __forceinline__ void fma2(u64 &d, u64 a, u64 b) {
    asm("fma.rn.f32x2 %0, %1, %2, %0;" : "+l"(d) : "l"(a), "l"(b));
}

// ---------------------------------------------------------------------------
// K1: build cost volume.
// ---------------------------------------------------------------------------
__global__ void k_build_cv(const float* __restrict__ x) {
    unsigned idx = blockIdx.x * blockDim.x + threadIdx.x;
    if (idx >= (unsigned)(BB*MCC*HWD)) return;
    unsigned i = idx;
    int d  = i % NDD;  i /= NDD;
    int w  = i % WW;   i /= WW;
    int h  = i % HH;   i /= HH;
    int mc = i % MCC;  i /= MCC;
    int b  = i;
    int m = mc / CCH, c = mc % CCH;
    int ws = w + (d - 4) * (m - 4);
    float v = 0.f;
    if ((unsigned)ws < WW)
        v = x[(((size_t)(b*CCH + c)*HH + h)*WW + ws)*MM + m];
    g_cv[idx] = v;
}

// ---------------------------------------------------------------------------
// K2: mean pool per (b,mc). Deterministic tree reduce.
// ---------------------------------------------------------------------------
__global__ void k_reduce() {
    int bm = blockIdx.x;
    const float* src = g_cv + (size_t)bm * HWD;
    float s = 0.f;
    for (int i = threadIdx.x; i < HWD; i += 256) s += src[i];
    __shared__ float sh[256];
    sh[threadIdx.x] = s;
    __syncthreads();
    for (int o = 128; o > 0; o >>= 1) {
        if (threadIdx.x < o) sh[threadIdx.x] += sh[threadIdx.x + o];
        __syncthreads();
    }
    if (threadIdx.x == 0) g_p[bm] = sh[0] * (1.0f / HWD);
}

// ---------------------------------------------------------------------------
// K3: global attention branch (center tap only at 1x1x1).
// ---------------------------------------------------------------------------
__global__ void k_global(const float* __restrict__ w1, const float* __restrict__ b1,
                         const float* __restrict__ g1, const float* __restrict__ be1,
                         const float* __restrict__ m1, const float* __restrict__ v1,
                         const float* __restrict__ w2, const float* __restrict__ b2,
                         const float* __restrict__ g2, const float* __restrict__ be2,
                         const float* __restrict__ m2, const float* __restrict__ v2) {
    __shared__ float gh[BB*HIDN];
    int t = threadIdx.x;
    if (t < BB*HIDN) {
        int b = t / HIDN, o = t % HIDN;
        float s = b1[o];
        for (int c = 0; c < MCC; c++)
            s += w1[(o*MCC + c)*27 + 13] * g_p[b*MCC + c];
        float sc = g1[o] * rsqrtf(v1[o] + EPSBN);
        s = (s - m1[o]) * sc + be1[o];
        gh[t] = fmaxf(s, 0.f);
    }
    __syncthreads();
    if (t < BB*MM) {
        int b = t / MM, og = t % MM;
        float s = b2[og];
        for (int o = 0; o < HIDN; o++)
            s += w2[(og*HIDN + o)*27 + 13] * gh[b*HIDN + o];
        float sc = g2[og] * rsqrtf(v2[og] + EPSBN);
        g_xg[t] = (s - m2[og]) * sc + be2[og];
    }
}

// ---------------------------------------------------------------------------
// K-pack: duplicate weights into {w,w} pairs for fma.rn.f32x2 operands.
// ---------------------------------------------------------------------------
__global__ void k_packw(const float* __restrict__ w1, const float* __restrict__ w2) {
    int t = blockIdx.x * 256 + threadIdx.x;
    if (t < 2*MCC*27*9) {
        int oc = t % 9; int r = t / 9;
        int tap = r % 27; r /= 27;
        int mc = r % MCC; int g = r / MCC;
        float v = w1[((size_t)((g*9+oc)*MCC + mc))*27 + tap];
        float* d = &g_w1p[((size_t)(g*MCC + mc)*27 + tap)*18 + 2*oc];
        d[0] = v; d[1] = v;
    }
    if (t < HIDN*27*9) {
        int oc = t % 9; int r = t / 9;
        int tap = r % 27; int ci = r / 27;
        float v = w2[((size_t)(oc*HIDN + ci))*27 + tap];
        float* d = &g_w2p[((size_t)ci*27 + tap)*18 + 2*oc];
        d[0] = v; d[1] = v;
    }
}

// ---------------------------------------------------------------------------
// K4/K5: 3x3x3 conv, register-blocked 9oc x 9d per thread, f32x2 packed over d.
// Block 128 thr = 16(w) x 8(h). Tile smem: [MCH][10h][18w][12z], z=d+1 (pads 0).
// FIRST=true : conv1 144->18 (NG=2 oc-groups), ReLU epilogue  -> g_h1
// FIRST=false: conv2 18->9  (NG=1), sigmoid(+global) epilogue -> g_wei
// ---------------------------------------------------------------------------
template<int CIN, int MCH, int NG, bool FIRST>
__global__ __launch_bounds__(128) void k_conv(
        const float* __restrict__ gam, const float* __restrict__ bet,
        const float* __restrict__ mu,  const float* __restrict__ var,
        const float* __restrict__ bias) {
    extern __shared__ float sm[];
    float* tile = sm;                        // MCH*10*18*12
    float* wsh  = sm + MCH*10*18*12;         // MCH*27*18

    const float* src = FIRST ? g_cv : g_h1;
    const float* wpk = FIRST ? g_w1p : g_w2p;
    float* dst       = FIRST ? g_h1 : g_wei;

    int tid = threadIdx.x;
    int tx = tid & 15, ty = tid >> 4;        // 16 x 8
    int gz = blockIdx.z;
    int b = gz / NG, g = gz % NG;
    int w0 = blockIdx.x * 16, h0 = blockIdx.y * 8;

    // zero tile once (z pads 0,10,11 and OOB stay zero; data region rewritten)
    for (int i = tid; i < MCH*10*18*12; i += 128) tile[i] = 0.f;

    u64 acc[9][5];
#pragma unroll
    for (int o = 0; o < 9; o++)
#pragma unroll
        for (int p = 0; p < 5; p++) acc[o][p] = 0ull;

    const float* srcb = src + (size_t)b*CIN*HWD;
    const float* wg   = wpk + (size_t)g*CIN*27*18;

    for (int c0 = 0; c0 < CIN; c0 += MCH) {
        __syncthreads();
        for (int i = tid; i < MCH*27*18; i += 128)
            wsh[i] = wg[(size_t)c0*27*18 + i];
        for (int i = tid; i < MCH*10*18*9; i += 128) {
            int d = i % 9; int r = i / 9;
            int wi = r % 18; r /= 18;
            int hi = r % 10; int mcl = r / 10;
            int h = h0 - 1 + hi, w = w0 - 1 + wi;
            float v = 0.f;
            if ((unsigned)h < HH && (unsigned)w < WW)
                v = srcb[(size_t)(c0 + mcl)*HWD + (h*WW + w)*9 + d];
            tile[((mcl*10 + hi)*18 + wi)*12 + d + 1] = v;
        }
        __syncthreads();
#pragma unroll 1
        for (int mcl = 0; mcl < MCH; mcl++) {
            const float* tb = tile + mcl*10*18*12;
            const float* wb = wsh  + mcl*27*18;
#pragma unroll
            for (int k0 = 0; k0 < 3; k0++)
#pragma unroll
            for (int k1 = 0; k1 < 3; k1++) {
                const float4* tp = (const float4*)(tb + ((ty + k0)*18 + (tx + k1))*12);
                float4 q0 = tp[0], q1 = tp[1], q2 = tp[2];
                float t[12] = {q0.x,q0.y,q0.z,q0.w, q1.x,q1.y,q1.z,q1.w,
                               q2.x,q2.y,q2.z,q2.w};
#pragma unroll
                for (int k2 = 0; k2 < 3; k2++) {
                    u64 xv[5];
#pragma unroll
                    for (int p = 0; p < 5; p++)
                        xv[p] = pk2(t[2*p + k2], t[2*p + k2 + 1]);
                    const u64* wrow = (const u64*)(wb + ((k0*3 + k1)*3 + k2)*18);
#pragma unroll
                    for (int o = 0; o < 9; o++) {
                        u64 wv = wrow[o];
#pragma unroll
                        for (int p = 0; p < 5; p++) fma2(acc[o][p], wv, xv[p]);
                    }
                }
            }
        }
    }

    int h = h0 + ty, w = w0 + tx;
#pragma unroll
    for (int o = 0; o < 9; o++) {
        int oc = g*9 + o;
        float s  = gam[oc] * rsqrtf(var[oc] + EPSBN);
        float bi = (bias[oc] - mu[oc]) * s + bet[oc];
        float xg = FIRST ? 0.f : g_xg[b*MM + oc];
        float* dp = dst + (size_t)(b*(NG*9) + oc)*HWD + (h*WW + w)*9;
#pragma unroll
        for (int p = 0; p < 5; p++) {
            float lo, hi;
            upk2(lo, hi, acc[o][p]);
            float y0 = lo*s + bi;
            if (FIRST) y0 = fmaxf(y0, 0.f);
            else       y0 = 1.f / (1.f + expf(-(y0 + xg)));
            dp[2*p] = y0;
            if (p < 4) {
                float y1 = hi*s + bi;
                if (FIRST) y1 = fmaxf(y1, 0.f);
                else       y1 = 1.f / (1.f + expf(-(y1 + xg)));
                dp[2*p + 1] = y1;
            }
        }
    }
}

// ---------------------------------------------------------------------------
// K6: conv_last GEMM with f32x2: Out[oc,p] = clb[oc] + sum_k W[oc,k]*A[k,p],
// A[k,p] = wei * cv. Thread: 10 oc-pairs x 4 p. Ws rows padded to 162.
// ---------------------------------------------------------------------------
extern __shared__ float sfin[];
__global__ __launch_bounds__(256) void k_final(
        const float* __restrict__ clw, const float* __restrict__ clb,
        float* __restrict__ out) {
    float* As = sfin;               // [144][128]
    float* Ws = sfin + 144*128;     // [144][162] (oc >= 150 zero)
    int b  = blockIdx.y;
    int p0 = blockIdx.x * 128;
    int tid = threadIdx.x;

    for (int t = tid; t < 162*144; t += 256) {
        int oc = t / 144, k = t % 144;        // k-coalesced LDG
        Ws[k*162 + oc] = (oc < OUTC) ? clw[oc*MCC + k] : 0.f;
    }
    const float* cvb = g_cv  + (size_t)b*MCC*HWD + p0;
    const float* wb  = g_wei + (size_t)b*MM *HWD + p0;
    for (int t = tid; t < 144*128; t += 256) {
        int k = t >> 7, p = t & 127;
        As[t] = cvb[(size_t)k*HWD + p] * wb[(size_t)(k >> 4)*HWD + p];
    }
    __syncthreads();

    int tx = tid & 31, ty = tid >> 5;
    u64 acc[10][4];
#pragma unroll
    for (int j = 0; j < 10; j++)
#pragma unroll
        for (int i = 0; i < 4; i++) acc[j][i] = 0ull;

#pragma unroll 2
    for (int k = 0; k < 144; k++) {
        float4 a = *(const float4*)(As + k*128 + tx*4);
        u64 a0 = pk2(a.x, a.x), a1 = pk2(a.y, a.y);
        u64 a2 = pk2(a.z, a.z), a3 = pk2(a.w, a.w);
        const u64* wrow = (const u64*)(Ws + k*162 + ty*20);
#pragma unroll
        for (int j = 0; j < 10; j++) {
            u64 wv = wrow[j];
            fma2(acc[j][0], wv, a0); fma2(acc[j][1], wv, a1);
            fma2(acc[j][2], wv, a2); fma2(acc[j][3], wv, a3);
        }
    }

#pragma unroll
    for (int j = 0; j < 10; j++) {
        int oc0 = ty*20 + 2*j;
        float lo[4], hi[4];
#pragma unroll
        for (int i = 0; i < 4; i++) upk2(lo[i], hi[i], acc[j][i]);
        if (oc0 < OUTC) {
            float bv = clb[oc0];
            float4 r = make_float4(lo[0]+bv, lo[1]+bv, lo[2]+bv, lo[3]+bv);
            *(float4*)(out + (size_t)(b*OUTC + oc0)*HWD + p0 + tx*4) = r;
        }
        if (oc0 + 1 < OUTC) {
            float bv = clb[oc0+1];
            float4 r = make_float4(hi[0]+bv, hi[1]+bv, hi[2]+bv, hi[3]+bv);
            *(float4*)(out + (size_t)(b*OUTC + oc0 + 1)*HWD + p0 + tx*4) = r;
        }
    }
}

// ---------------------------------------------------------------------------
extern "C" void kernel_launch(void* const* d_in, const int* in_sizes, int n_in,
                              void* d_out, int out_size) {
    const float* x      = (const float*)d_in[0];
    const float* la_w1  = (const float*)d_in[1];
    const float* la_b1  = (const float*)d_in[2];
    const float* la_g1  = (const float*)d_in[3];
    const float* la_be1 = (const float*)d_in[4];
    const float* la_m1  = (const float*)d_in[5];
    const float* la_v1  = (const float*)d_in[6];
    const float* la_w2  = (const float*)d_in[7];
    const float* la_b2  = (const float*)d_in[8];
    const float* la_g2  = (const float*)d_in[9];
    const float* la_be2 = (const float*)d_in[10];
    const float* la_m2  = (const float*)d_in[11];
    const float* la_v2  = (const float*)d_in[12];
    const float* ga_w1  = (const float*)d_in[13];
    const float* ga_b1  = (const float*)d_in[14];
    const float* ga_g1  = (const float*)d_in[15];
    const float* ga_be1 = (const float*)d_in[16];
    const float* ga_m1  = (const float*)d_in[17];
    const float* ga_v1  = (const float*)d_in[18];
    const float* ga_w2  = (const float*)d_in[19];
    const float* ga_b2  = (const float*)d_in[20];
    const float* ga_g2  = (const float*)d_in[21];
    const float* ga_be2 = (const float*)d_in[22];
    const float* ga_m2  = (const float*)d_in[23];
    const float* ga_v2  = (const float*)d_in[24];
    const float* cl_w   = (const float*)d_in[25];
    const float* cl_b   = (const float*)d_in[26];
    float* out = (float*)d_out;

    const int smem_c1 = (8*10*18*12 + 8*27*18) * 4;      // 84672
    const int smem_c2 = (6*10*18*12 + 6*27*18) * 4;      // 63504
    const int smem_fin = (144*128 + 144*162) * 4;        // 167040
    cudaFuncSetAttribute(k_conv<MCC, 8, 2, true>,  cudaFuncAttributeMaxDynamicSharedMemorySize, smem_c1);
    cudaFuncSetAttribute(k_conv<HIDN, 6, 1, false>, cudaFuncAttributeMaxDynamicSharedMemorySize, smem_c2);
    cudaFuncSetAttribute(k_final, cudaFuncAttributeMaxDynamicSharedMemorySize, smem_fin);

    unsigned ncv = BB*MCC*HWD;
    k_build_cv<<<(ncv + 255)/256, 256>>>(x);
    k_reduce<<<BB*MCC, 256>>>();
    k_global<<<1, 64>>>(ga_w1, ga_b1, ga_g1, ga_be1, ga_m1, ga_v1,
                        ga_w2, ga_b2, ga_g2, ga_be2, ga_m2, ga_v2);
    k_packw<<<(2*MCC*27*9 + 255)/256, 256>>>(la_w1, la_w2);

    dim3 g1(WW/16, HH/8, BB*2);
    k_conv<MCC, 8, 2, true><<<g1, 128, smem_c1>>>(la_g1, la_be1, la_m1, la_v1, la_b1);
    dim3 g2(WW/16, HH/8, BB*1);
    k_conv<HIDN, 6, 1, false><<<g2, 128, smem_c2>>>(la_g2, la_be2, la_m2, la_v2, la_b2);

    dim3 gf(HWD/128, BB);
    k_final<<<gf, 256, smem_fin>>>(cl_w, cl_b, out);
}